// round 14
// baseline (speedup 1.0000x reference)
#include <cuda_runtime.h>
#include <cuda_bf16.h>
#include <cuda_fp8.h>
#include <cstdint>

#define N 4096
#define D 512
#define NN ((size_t)N * (size_t)N)
#define OUT_P 1
#define OUT_C (1 + 16777216)
#define KSCALE 64.0f
#define FP8_ITERS 8
#define BF16_ITERS 2

// ---- device scratch (no allocations allowed) ----
__device__ __align__(16) __nv_bfloat16 g_Kb[NN];            // 32 MB bf16 K
__device__ __align__(16) __nv_bfloat16 g_KT[NN];            // 32 MB bf16 K^T
__device__ __align__(16) uint8_t g_K8[NN];                  // 16 MB fp8 Ks = 64*K
__device__ __align__(16) uint8_t g_KT8[NN];                 // 16 MB fp8 Ks^T
__device__ __align__(16) __nv_bfloat16 g_Sb[(size_t)N * D];
__device__ __align__(16) __nv_bfloat16 g_Tb[(size_t)N * D];
__device__ __align__(16) float g_sn[N], g_tn[N];
__device__ __align__(16) float g_u[N], g_v[N];
__device__ __align__(16) float g_part[N];

// ---- L2 evict_last via cache-hint policy ----
__device__ __forceinline__ uint64_t evict_last_policy() {
    uint64_t pol;
    asm("createpolicy.fractional.L2::evict_last.b64 %0, 1.0;" : "=l"(pol));
    return pol;
}
__device__ __forceinline__ uint4 ldG16(const void* p, uint64_t pol) {
    uint4 r;
    asm volatile("ld.global.nc.L2::cache_hint.v4.u32 {%0,%1,%2,%3}, [%4], %5;"
                 : "=r"(r.x), "=r"(r.y), "=r"(r.z), "=r"(r.w)
                 : "l"(p), "l"(pol));
    return r;
}
__device__ __forceinline__ void stG2(void* p, uint16_t v, uint64_t pol) {
    asm volatile("st.global.L2::cache_hint.u16 [%0], %1, %2;"
                 :: "l"(p), "h"(v), "l"(pol));
}
__device__ __forceinline__ void stG4(void* p, uint32_t v, uint64_t pol) {
    asm volatile("st.global.L2::cache_hint.u32 [%0], %1, %2;"
                 :: "l"(p), "r"(v), "l"(pol));
}
__device__ __forceinline__ void stG8(void* p, uint2 v, uint64_t pol) {
    asm volatile("st.global.L2::cache_hint.v2.u32 [%0], {%1,%2}, %3;"
                 :: "l"(p), "r"(v.x), "r"(v.y), "l"(pol));
}
__device__ __forceinline__ void stG16(void* p, uint4 v, uint64_t pol) {
    asm volatile("st.global.L2::cache_hint.v4.u32 [%0], {%1,%2,%3,%4}, %5;"
                 :: "l"(p), "r"(v.x), "r"(v.y), "r"(v.z), "r"(v.w), "l"(pol));
}

// bf16 m16n8k16 mma, fp32 accumulate
__device__ __forceinline__ void mma16(float* c, const uint32_t* a, const uint32_t* b) {
    asm volatile(
        "mma.sync.aligned.m16n8k16.row.col.f32.bf16.bf16.f32 "
        "{%0,%1,%2,%3},{%4,%5,%6,%7},{%8,%9},{%0,%1,%2,%3};"
        : "+f"(c[0]), "+f"(c[1]), "+f"(c[2]), "+f"(c[3])
        : "r"(a[0]), "r"(a[1]), "r"(a[2]), "r"(a[3]), "r"(b[0]), "r"(b[1]));
}

// ---- fused convert fp32->bf16 + row sq-norms (+ optional v0 = 1) ----
__global__ void cvt_norm_kernel(const float* __restrict__ X, __nv_bfloat16* __restrict__ Y,
                                float* __restrict__ nrm, int setv) {
    __shared__ float ws[8];
    int tid = threadIdx.x;
    if (setv && blockIdx.x < 16) g_v[blockIdx.x * 256 + tid] = 1.0f;
    size_t base = (size_t)blockIdx.x * 1024 + tid * 4;
    float4 a = *(const float4*)(X + base);
    uint2 o;
    __nv_bfloat162 lo = __floats2bfloat162_rn(a.x, a.y);
    __nv_bfloat162 hi = __floats2bfloat162_rn(a.z, a.w);
    o.x = *(uint32_t*)&lo;
    o.y = *(uint32_t*)&hi;
    *(uint2*)(Y + base) = o;
    float s = a.x * a.x + a.y * a.y + a.z * a.z + a.w * a.w;
#pragma unroll
    for (int of = 16; of > 0; of >>= 1) s += __shfl_xor_sync(0xffffffffu, s, of);
    if ((tid & 31) == 0) ws[tid >> 5] = s;
    __syncthreads();
    if (tid == 0)   nrm[blockIdx.x * 2]     = ws[0] + ws[1] + ws[2] + ws[3];
    if (tid == 128) nrm[blockIdx.x * 2 + 1] = ws[4] + ws[5] + ws[6] + ws[7];
}

// ---- bf16 tensor-core GEMM + epilogue writing C, Kbf, K8, KTbf, KT8 ----
__global__ void __launch_bounds__(256) gemm_kernel(float* __restrict__ out) {
    __shared__ __align__(16) char smem_all[2 * 128 * 80 * 2];
    char (*As)[128 * 80] = (char(*)[128 * 80])smem_all;
    char (*Bs)[128 * 80] = (char(*)[128 * 80])(smem_all + 2 * 128 * 80);
    const int tid  = threadIdx.x;
    const int lane = tid & 31, warp = tid >> 5;
    const int wm = warp & 1, wn = warp >> 1;
    const int quad = lane >> 2, tb = (lane & 3) * 4;
    const int bi = blockIdx.y, bj = blockIdx.x;

    float acc[4][4][4];
#pragma unroll
    for (int a = 0; a < 4; a++)
#pragma unroll
        for (int b = 0; b < 4; b++)
#pragma unroll
            for (int r = 0; r < 4; r++) acc[a][b][r] = 0.f;

    const __nv_bfloat16* Sb = g_Sb + (size_t)bi * 128 * D;
    const __nv_bfloat16* Tb = g_Tb + (size_t)bj * 128 * D;

    auto load_chunk = [&](int kc, int buf) {
#pragma unroll
        for (int q = 0; q < 2; q++) {
            int f = tid + 256 * q;
            int r = f >> 2, seg = f & 3;
            const __nv_bfloat16* sa = Sb + (size_t)r * D + kc + seg * 8;
            const __nv_bfloat16* sb = Tb + (size_t)r * D + kc + seg * 8;
            uint32_t da = (uint32_t)__cvta_generic_to_shared(&As[buf][r * 80 + seg * 16]);
            uint32_t db = (uint32_t)__cvta_generic_to_shared(&Bs[buf][r * 80 + seg * 16]);
            asm volatile("cp.async.cg.shared.global [%0], [%1], 16;\n\t"
                         "cp.async.cg.shared.global [%2], [%3], 16;"
                         :: "r"(da), "l"(sa), "r"(db), "l"(sb));
        }
        asm volatile("cp.async.commit_group;");
    };

    load_chunk(0, 0);
    for (int c = 0; c < 16; c++) {
        if (c + 1 < 16) {
            load_chunk((c + 1) * 32, (c + 1) & 1);
            asm volatile("cp.async.wait_group 1;");
        } else {
            asm volatile("cp.async.wait_group 0;");
        }
        __syncthreads();
        const char* Ab = As[c & 1];
        const char* Bb = Bs[c & 1];
#pragma unroll
        for (int s = 0; s < 2; s++) {
            const int kb = s * 32 + tb;
            uint32_t aF[4][4], bF[4][2];
#pragma unroll
            for (int mi = 0; mi < 4; mi++) {
                int row = wm * 64 + mi * 16 + quad;
                aF[mi][0] = *(const uint32_t*)(Ab + row * 80 + kb);
                aF[mi][1] = *(const uint32_t*)(Ab + (row + 8) * 80 + kb);
                aF[mi][2] = *(const uint32_t*)(Ab + row * 80 + kb + 16);
                aF[mi][3] = *(const uint32_t*)(Ab + (row + 8) * 80 + kb + 16);
            }
#pragma unroll
            for (int ni = 0; ni < 4; ni++) {
                int nr = wn * 32 + ni * 8 + quad;
                bF[ni][0] = *(const uint32_t*)(Bb + nr * 80 + kb);
                bF[ni][1] = *(const uint32_t*)(Bb + nr * 80 + kb + 16);
            }
#pragma unroll
            for (int mi = 0; mi < 4; mi++)
#pragma unroll
                for (int ni = 0; ni < 4; ni++) mma16(acc[mi][ni], aF[mi], bF[ni]);
        }
        __syncthreads();
    }
    __syncthreads();   // mainloop buffers dead; reuse as bf16 K^T staging tile

    __nv_bfloat16* ktbuf = (__nv_bfloat16*)smem_all;   // [128][136] bf16 (34816 B)
    uint64_t pol = evict_last_policy();
    float* outC = out + OUT_C;
#pragma unroll
    for (int mi = 0; mi < 4; mi++) {
#pragma unroll
        for (int ni = 0; ni < 4; ni++) {
            int rl0 = wm * 64 + mi * 16 + quad;
            int cl  = wn * 32 + ni * 8 + (lane & 3) * 2;
            int row0 = bi * 128 + rl0;
            int col  = bj * 128 + cl;
#pragma unroll
            for (int h = 0; h < 2; h++) {
                int rr = row0 + h * 8, rl = rl0 + h * 8;
                float d0 = acc[mi][ni][2 * h], d1 = acc[mi][ni][2 * h + 1];
                float sn = g_sn[rr];
                float c0 = sqrtf(fmaxf(sn + g_tn[col]     - 2.f * d0, 0.f));
                float c1 = sqrtf(fmaxf(sn + g_tn[col + 1] - 2.f * d1, 0.f));
                __stcs(&outC[(size_t)rr * N + col],     c0);
                __stcs(&outC[(size_t)rr * N + col + 1], c1);
                float e0 = __expf(-0.125f * c0), e1 = __expf(-0.125f * c1);
                __nv_bfloat162 kk = __floats2bfloat162_rn(e0, e1);
                stG4(&g_Kb[(size_t)rr * N + col], *(uint32_t*)&kk, pol);
                __nv_fp8x2_storage_t k8 = __nv_cvt_float2_to_fp8x2(
                    make_float2(KSCALE * e0, KSCALE * e1), __NV_SATFINITE, __NV_E4M3);
                stG2(&g_K8[(size_t)rr * N + col], (uint16_t)k8, pol);
                ktbuf[cl * 136 + rl]       = kk.x;   // transposed bf16 staging
                ktbuf[(cl + 1) * 136 + rl] = kk.y;
            }
        }
    }
    __syncthreads();
    // coalesced K^T writes (bf16 + derived fp8): 2048 x (16B bf16 / 8B fp8)
#pragma unroll
    for (int q = 0; q < 8; q++) {
        int idx = tid + 256 * q;            // 0..2047
        int j = idx >> 4, seg = idx & 15;
        uint4 v = *(const uint4*)&ktbuf[j * 136 + seg * 8];
        size_t off = (size_t)(bj * 128 + j) * N + bi * 128 + seg * 8;
        stG16(&g_KT[off], v, pol);
        // convert 8 bf16 -> 8 fp8 (Ks = 64*K)
        const uint32_t w[4] = {v.x, v.y, v.z, v.w};
        uint2 p8;
        uint8_t b8[8];
#pragma unroll
        for (int t = 0; t < 4; t++) {
            float2 f = __bfloat1622float2(*(__nv_bfloat162*)&w[t]);
            __nv_fp8x2_storage_t k8 = __nv_cvt_float2_to_fp8x2(
                make_float2(KSCALE * f.x, KSCALE * f.y), __NV_SATFINITE, __NV_E4M3);
            b8[2 * t]     = (uint8_t)(k8 & 0xFF);
            b8[2 * t + 1] = (uint8_t)(k8 >> 8);
        }
        p8.x = b8[0] | (b8[1] << 8) | (b8[2] << 16) | ((uint32_t)b8[3] << 24);
        p8.y = b8[4] | (b8[5] << 8) | (b8[6] << 16) | ((uint32_t)b8[7] << 24);
        stG8(&g_KT8[off], p8, pol);
    }
}

// ---- fp8 scaling pass: o[r] = (1/N) / (sum_j M[r][j]*x[j] + stab) ----
__global__ void row8_kernel(const uint8_t* __restrict__ M,
                            const float* __restrict__ xin,
                            float* __restrict__ xout) {
    __shared__ float vs[N];
    __shared__ float ps[8];
    int tid = threadIdx.x;
#pragma unroll
    for (int q = 0; q < 4; q++) {
        int f = tid + 256 * q;
        ((float4*)vs)[f] = ((const float4*)xin)[f];
    }
    __syncthreads();
    uint64_t pol = evict_last_policy();
    int lane = tid & 31, warp = tid >> 5;
    int row  = blockIdx.x * 4 + (warp >> 1);
    int half = warp & 1;
    const uint8_t* Kr = M + (size_t)row * N + half * 2048 + lane * 16;
    const float* vh = vs + half * 2048 + lane * 16;

    uint4 kr[4];
#pragma unroll
    for (int c = 0; c < 4; c++) kr[c] = ldG16(Kr + c * 512, pol);

    float s = 0.f;
#pragma unroll
    for (int c = 0; c < 4; c++) {
        const uint32_t w[4] = {kr[c].x, kr[c].y, kr[c].z, kr[c].w};
#pragma unroll
        for (int t = 0; t < 4; t++) {
            __half2_raw r0 = __nv_cvt_fp8x2_to_halfraw2(
                (__nv_fp8x2_storage_t)(w[t] & 0xFFFF), __NV_E4M3);
            __half2_raw r1 = __nv_cvt_fp8x2_to_halfraw2(
                (__nv_fp8x2_storage_t)(w[t] >> 16), __NV_E4M3);
            float2 f01 = __half22float2(*(__half2*)&r0);
            float2 f23 = __half22float2(*(__half2*)&r1);
            float4 vv = *(const float4*)(vh + c * 512 + t * 4);
            s += f01.x * vv.x + f01.y * vv.y + f23.x * vv.z + f23.y * vv.w;
        }
    }
#pragma unroll
    for (int o = 16; o > 0; o >>= 1) s += __shfl_xor_sync(0xffffffffu, s, o);
    if (lane == 0) ps[warp] = s;
    __syncthreads();
    if (tid < 4)
        xout[blockIdx.x * 4 + tid] = (1.0f / N) / (ps[2 * tid] + ps[2 * tid + 1] + 1e-8f);
}

// ---- bf16 scaling pass (final iterations) ----
__global__ void row_kernel(const __nv_bfloat16* __restrict__ M,
                           const float* __restrict__ xin,
                           float* __restrict__ xout) {
    __shared__ float vs[N];
    __shared__ float ps[8];
    int tid = threadIdx.x;
#pragma unroll
    for (int q = 0; q < 4; q++) {
        int f = tid + 256 * q;
        ((float4*)vs)[f] = ((const float4*)xin)[f];
    }
    __syncthreads();
    uint64_t pol = evict_last_policy();
    int lane = tid & 31, warp = tid >> 5;
    int row  = blockIdx.x * 4 + (warp >> 1);
    int half = warp & 1;
    const __nv_bfloat16* Kr = M + (size_t)row * N + half * 2048 + lane * 8;
    const float* vh = vs + half * 2048 + lane * 8;

    uint4 kr[8];
#pragma unroll
    for (int c = 0; c < 8; c++) kr[c] = ldG16(Kr + c * 256, pol);

    float s = 0.f;
#pragma unroll
    for (int c = 0; c < 8; c++) {
        float2 f0 = __bfloat1622float2(*reinterpret_cast<__nv_bfloat162*>(&kr[c].x));
        float2 f1 = __bfloat1622float2(*reinterpret_cast<__nv_bfloat162*>(&kr[c].y));
        float2 f2 = __bfloat1622float2(*reinterpret_cast<__nv_bfloat162*>(&kr[c].z));
        float2 f3 = __bfloat1622float2(*reinterpret_cast<__nv_bfloat162*>(&kr[c].w));
        float4 va = *(const float4*)(vh + c * 256);
        float4 vb = *(const float4*)(vh + c * 256 + 4);
        s += f0.x * va.x + f0.y * va.y + f1.x * va.z + f1.y * va.w;
        s += f2.x * vb.x + f2.y * vb.y + f3.x * vb.z + f3.y * vb.w;
    }
#pragma unroll
    for (int o = 16; o > 0; o >>= 1) s += __shfl_xor_sync(0xffffffffu, s, o);
    if (lane == 0) ps[warp] = s;
    __syncthreads();
    if (tid < 4)
        xout[blockIdx.x * 4 + tid] = (1.0f / N) / (ps[2 * tid] + ps[2 * tid + 1] + 1e-8f);
}

// ---- coupling = u * exp(-C/8) * v ; vectorized around the +1 misalignment ----
__global__ void final_kernel(float* __restrict__ out) {
    int row = blockIdx.x, tid = threadIdx.x;
    float u = g_u[row];      // final iterations are bf16 -> u unscaled
    const float* Crow = out + OUT_C + (size_t)row * N;
    float* Prow = out + OUT_P + (size_t)row * N;
    float ls = 0.f;
    if (tid == 0) {
#pragma unroll
        for (int j = 0; j < 3; j++) {
            float C = Crow[j];
            float cp = u * __expf(-0.125f * C) * g_v[j];
            Prow[j] = cp;
            ls += cp * C;
        }
    } else if (tid == 1) {
        float C = Crow[4095];
        float cp = u * __expf(-0.125f * C) * g_v[4095];
        Prow[4095] = cp;
        ls += cp * C;
    }
#pragma unroll 4
    for (int q = tid; q < 1023; q += 256) {
        int j = 3 + 4 * q;
        float4 C4 = __ldcs((const float4*)(Crow + j));
        float4 p;
        p.x = u * __expf(-0.125f * C4.x) * g_v[j];
        p.y = u * __expf(-0.125f * C4.y) * g_v[j + 1];
        p.z = u * __expf(-0.125f * C4.z) * g_v[j + 2];
        p.w = u * __expf(-0.125f * C4.w) * g_v[j + 3];
        __stcs((float4*)(Prow + j), p);
        ls += p.x * C4.x + p.y * C4.y + p.z * C4.z + p.w * C4.w;
    }
    __shared__ float red[256];
    red[tid] = ls;
    __syncthreads();
    for (int o = 128; o > 0; o >>= 1) {
        if (tid < o) red[tid] += red[tid + o];
        __syncthreads();
    }
    if (tid == 0) g_part[row] = red[0];
}

__global__ void loss_kernel(float* __restrict__ out) {
    int tid = threadIdx.x;
    float s = 0.f;
#pragma unroll
    for (int q = 0; q < 16; q++) s += g_part[tid + q * 256];
    __shared__ float red[256];
    red[tid] = s;
    __syncthreads();
    for (int o = 128; o > 0; o >>= 1) {
        if (tid < o) red[tid] += red[tid + o];
        __syncthreads();
    }
    if (tid == 0) out[0] = red[0] * (1.0f / ((float)N * (float)N));
}

extern "C" void kernel_launch(void* const* d_in, const int* in_sizes, int n_in,
                              void* d_out, int out_size) {
    const float* S  = (const float*)d_in[0];
    const float* Tm = (const float*)d_in[1];
    float* out = (float*)d_out;

    __nv_bfloat16 *dSb, *dTb, *dK, *dKT;
    uint8_t *dK8, *dKT8;
    float *dSn, *dTn, *dU, *dV;
    cudaGetSymbolAddress((void**)&dSb,  g_Sb);
    cudaGetSymbolAddress((void**)&dTb,  g_Tb);
    cudaGetSymbolAddress((void**)&dK,   g_Kb);
    cudaGetSymbolAddress((void**)&dKT,  g_KT);
    cudaGetSymbolAddress((void**)&dK8,  g_K8);
    cudaGetSymbolAddress((void**)&dKT8, g_KT8);
    cudaGetSymbolAddress((void**)&dSn,  g_sn);
    cudaGetSymbolAddress((void**)&dTn,  g_tn);
    cudaGetSymbolAddress((void**)&dU,   g_u);
    cudaGetSymbolAddress((void**)&dV,   g_v);

    cvt_norm_kernel<<<2048, 256>>>(S, dSb, dSn, 0);
    cvt_norm_kernel<<<2048, 256>>>(Tm, dTb, dTn, 1);
    gemm_kernel<<<dim3(32, 32), 256>>>(out);
    // iterations 1..8: fp8 (noise contracted away by the bf16 tail)
    for (int it = 0; it < FP8_ITERS; it++) {
        row8_kernel<<<1024, 256>>>(dK8,  dV, dU);   // u' = a/(Ks v)
        row8_kernel<<<1024, 256>>>(dKT8, dU, dV);   // v  = b/(Ks^T u')  (exact scale)
    }
    // iterations 9..10: bf16 (final u,v carry only bf16-grade error)
    for (int it = 0; it < BF16_ITERS; it++) {
        row_kernel<<<1024, 256>>>(dK,  dV, dU);     // u = a/(K v)
        row_kernel<<<1024, 256>>>(dKT, dU, dV);     // v = b/(K^T u)
    }
    final_kernel<<<4096, 256>>>(out);
    loss_kernel<<<1, 256>>>(out);
}

// round 15
// speedup vs baseline: 1.2635x; 1.2635x over previous
#include <cuda_runtime.h>
#include <cuda_bf16.h>
#include <cstdint>

#define N 4096
#define D 512
#define NN ((size_t)N * (size_t)N)
#define OUT_P 1
#define OUT_C (1 + 16777216)
#define GSMEM 61440   // 3-stage pipeline: 3 x (A 10240B + B 10240B)

// ---- device scratch (no allocations allowed) ----
__device__ __align__(16) __nv_bfloat16 g_Kb[NN];            // 32 MB bf16 K
__device__ __align__(16) __nv_bfloat16 g_KT[NN];            // 32 MB bf16 K^T
__device__ __align__(16) __nv_bfloat16 g_Sb[(size_t)N * D];
__device__ __align__(16) __nv_bfloat16 g_Tb[(size_t)N * D];
__device__ __align__(16) float g_sn[N], g_tn[N];
__device__ __align__(16) float g_u[N], g_v[N];
__device__ __align__(16) float g_part[N];

// ---- L2 evict_last via cache-hint policy ----
__device__ __forceinline__ uint64_t evict_last_policy() {
    uint64_t pol;
    asm("createpolicy.fractional.L2::evict_last.b64 %0, 1.0;" : "=l"(pol));
    return pol;
}
__device__ __forceinline__ uint4 ldG16(const void* p, uint64_t pol) {
    uint4 r;
    asm volatile("ld.global.nc.L2::cache_hint.v4.u32 {%0,%1,%2,%3}, [%4], %5;"
                 : "=r"(r.x), "=r"(r.y), "=r"(r.z), "=r"(r.w)
                 : "l"(p), "l"(pol));
    return r;
}
__device__ __forceinline__ void stG4(void* p, uint32_t v, uint64_t pol) {
    asm volatile("st.global.L2::cache_hint.u32 [%0], %1, %2;"
                 :: "l"(p), "r"(v), "l"(pol));
}
__device__ __forceinline__ void stG16(void* p, uint4 v, uint64_t pol) {
    asm volatile("st.global.L2::cache_hint.v4.u32 [%0], {%1,%2,%3,%4}, %5;"
                 :: "l"(p), "r"(v.x), "r"(v.y), "r"(v.z), "r"(v.w), "l"(pol));
}

// bf16 m16n8k16 mma, fp32 accumulate
__device__ __forceinline__ void mma16(float* c, const uint32_t* a, const uint32_t* b) {
    asm volatile(
        "mma.sync.aligned.m16n8k16.row.col.f32.bf16.bf16.f32 "
        "{%0,%1,%2,%3},{%4,%5,%6,%7},{%8,%9},{%0,%1,%2,%3};"
        : "+f"(c[0]), "+f"(c[1]), "+f"(c[2]), "+f"(c[3])
        : "r"(a[0]), "r"(a[1]), "r"(a[2]), "r"(a[3]), "r"(b[0]), "r"(b[1]));
}

// ---- fused convert fp32->bf16 + row sq-norms (+ optional v0 = 1) ----
__global__ void cvt_norm_kernel(const float* __restrict__ X, __nv_bfloat16* __restrict__ Y,
                                float* __restrict__ nrm, int setv) {
    __shared__ float ws[8];
    int tid = threadIdx.x;
    if (setv && blockIdx.x < 16) g_v[blockIdx.x * 256 + tid] = 1.0f;
    size_t base = (size_t)blockIdx.x * 1024 + tid * 4;
    float4 a = *(const float4*)(X + base);
    uint2 o;
    __nv_bfloat162 lo = __floats2bfloat162_rn(a.x, a.y);
    __nv_bfloat162 hi = __floats2bfloat162_rn(a.z, a.w);
    o.x = *(uint32_t*)&lo;
    o.y = *(uint32_t*)&hi;
    *(uint2*)(Y + base) = o;
    float s = a.x * a.x + a.y * a.y + a.z * a.z + a.w * a.w;
#pragma unroll
    for (int of = 16; of > 0; of >>= 1) s += __shfl_xor_sync(0xffffffffu, s, of);
    if ((tid & 31) == 0) ws[tid >> 5] = s;
    __syncthreads();
    if (tid == 0)   nrm[blockIdx.x * 2]     = ws[0] + ws[1] + ws[2] + ws[3];
    if (tid == 128) nrm[blockIdx.x * 2 + 1] = ws[4] + ws[5] + ws[6] + ws[7];
}

// ---- bf16 tensor-core GEMM: 3-stage cp.async pipeline, 1 barrier/chunk ----
// dyn layout: A bufs [0,3x10240), B bufs [30720, +3x10240). Epilogue reuses
// the region as bf16 K^T staging tile [128][136].
__global__ void __launch_bounds__(256) gemm_kernel(float* __restrict__ out) {
    extern __shared__ __align__(16) char dyn[];
    const int tid  = threadIdx.x;
    const int lane = tid & 31, warp = tid >> 5;
    const int wm = warp & 1, wn = warp >> 1;
    const int quad = lane >> 2, tb = (lane & 3) * 4;
    const int bi = blockIdx.y, bj = blockIdx.x;

    float acc[4][4][4];
#pragma unroll
    for (int a = 0; a < 4; a++)
#pragma unroll
        for (int b = 0; b < 4; b++)
#pragma unroll
            for (int r = 0; r < 4; r++) acc[a][b][r] = 0.f;

    const __nv_bfloat16* Sb = g_Sb + (size_t)bi * 128 * D;
    const __nv_bfloat16* Tb = g_Tb + (size_t)bj * 128 * D;

    auto load_chunk = [&](int kc, int buf) {
        char* Ab = dyn + buf * 10240;
        char* Bb = dyn + 30720 + buf * 10240;
#pragma unroll
        for (int q = 0; q < 2; q++) {
            int f = tid + 256 * q;
            int r = f >> 2, seg = f & 3;
            const __nv_bfloat16* sa = Sb + (size_t)r * D + kc + seg * 8;
            const __nv_bfloat16* sb = Tb + (size_t)r * D + kc + seg * 8;
            uint32_t da = (uint32_t)__cvta_generic_to_shared(Ab + r * 80 + seg * 16);
            uint32_t db = (uint32_t)__cvta_generic_to_shared(Bb + r * 80 + seg * 16);
            asm volatile("cp.async.cg.shared.global [%0], [%1], 16;\n\t"
                         "cp.async.cg.shared.global [%2], [%3], 16;"
                         :: "r"(da), "l"(sa), "r"(db), "l"(sb));
        }
        asm volatile("cp.async.commit_group;");
    };

    load_chunk(0, 0);
    load_chunk(32, 1);
    for (int c = 0; c < 16; c++) {
        if (c < 15) asm volatile("cp.async.wait_group 1;");
        else        asm volatile("cp.async.wait_group 0;");
        __syncthreads();
        if (c + 2 < 16) load_chunk((c + 2) * 32, (c + 2) % 3);   // overlaps MMA below
        const char* Ab = dyn + (c % 3) * 10240;
        const char* Bb = dyn + 30720 + (c % 3) * 10240;
#pragma unroll
        for (int s = 0; s < 2; s++) {
            const int kb = s * 32 + tb;
            uint32_t aF[4][4], bF[4][2];
#pragma unroll
            for (int mi = 0; mi < 4; mi++) {
                int row = wm * 64 + mi * 16 + quad;
                aF[mi][0] = *(const uint32_t*)(Ab + row * 80 + kb);
                aF[mi][1] = *(const uint32_t*)(Ab + (row + 8) * 80 + kb);
                aF[mi][2] = *(const uint32_t*)(Ab + row * 80 + kb + 16);
                aF[mi][3] = *(const uint32_t*)(Ab + (row + 8) * 80 + kb + 16);
            }
#pragma unroll
            for (int ni = 0; ni < 4; ni++) {
                int nr = wn * 32 + ni * 8 + quad;
                bF[ni][0] = *(const uint32_t*)(Bb + nr * 80 + kb);
                bF[ni][1] = *(const uint32_t*)(Bb + nr * 80 + kb + 16);
            }
#pragma unroll
            for (int mi = 0; mi < 4; mi++)
#pragma unroll
                for (int ni = 0; ni < 4; ni++) mma16(acc[mi][ni], aF[mi], bF[ni]);
        }
    }
    __syncthreads();   // pipeline drained; reuse smem as ktbuf

    __nv_bfloat16* ktbuf = (__nv_bfloat16*)dyn;   // [128][136] bf16 (34816 B)
    uint64_t pol = evict_last_policy();
    float* outC = out + OUT_C;
#pragma unroll
    for (int mi = 0; mi < 4; mi++) {
#pragma unroll
        for (int ni = 0; ni < 4; ni++) {
            int rl0 = wm * 64 + mi * 16 + quad;
            int cl  = wn * 32 + ni * 8 + (lane & 3) * 2;
            int row0 = bi * 128 + rl0;
            int col  = bj * 128 + cl;
#pragma unroll
            for (int h = 0; h < 2; h++) {
                int rr = row0 + h * 8, rl = rl0 + h * 8;
                float d0 = acc[mi][ni][2 * h], d1 = acc[mi][ni][2 * h + 1];
                float sn = g_sn[rr];
                float c0 = sqrtf(fmaxf(sn + g_tn[col]     - 2.f * d0, 0.f));
                float c1 = sqrtf(fmaxf(sn + g_tn[col + 1] - 2.f * d1, 0.f));
                __stcs(&outC[(size_t)rr * N + col],     c0);
                __stcs(&outC[(size_t)rr * N + col + 1], c1);
                __nv_bfloat162 kk = __floats2bfloat162_rn(__expf(-0.125f * c0),
                                                          __expf(-0.125f * c1));
                stG4(&g_Kb[(size_t)rr * N + col], *(uint32_t*)&kk, pol);
                ktbuf[cl * 136 + rl]       = kk.x;   // transposed staging
                ktbuf[(cl + 1) * 136 + rl] = kk.y;
            }
        }
    }
    __syncthreads();
    // coalesced K^T writes: row j of tile -> g_KT[(bj*128+j)*N + bi*128 ..]
#pragma unroll
    for (int q = 0; q < 8; q++) {
        int idx = tid + 256 * q;            // 0..2047
        int j = idx >> 4, seg = idx & 15;
        uint4 v = *(const uint4*)&ktbuf[j * 136 + seg * 8];
        stG16(&g_KT[(size_t)(bj * 128 + j) * N + bi * 128 + seg * 8], v, pol);
    }
}

// ---- scaling pass: o[r] = (1/N) / (sum_j M[r][j] * x[j] + stab) ----
// half-row per warp; all 8 K loads batched up-front.
__global__ void row_kernel(const __nv_bfloat16* __restrict__ M,
                           const float* __restrict__ xin,
                           float* __restrict__ xout) {
    __shared__ float vs[N];
    __shared__ float ps[8];
    int tid = threadIdx.x;
#pragma unroll
    for (int q = 0; q < 4; q++) {
        int f = tid + 256 * q;
        ((float4*)vs)[f] = ((const float4*)xin)[f];
    }
    __syncthreads();
    uint64_t pol = evict_last_policy();
    int lane = tid & 31, warp = tid >> 5;
    int row  = blockIdx.x * 4 + (warp >> 1);
    int half = warp & 1;
    const __nv_bfloat16* Kr = M + (size_t)row * N + half * 2048 + lane * 8;
    const float* vh = vs + half * 2048 + lane * 8;

    uint4 kr[8];
#pragma unroll
    for (int c = 0; c < 8; c++) kr[c] = ldG16(Kr + c * 256, pol);

    float s = 0.f;
#pragma unroll
    for (int c = 0; c < 8; c++) {
        float2 f0 = __bfloat1622float2(*reinterpret_cast<__nv_bfloat162*>(&kr[c].x));
        float2 f1 = __bfloat1622float2(*reinterpret_cast<__nv_bfloat162*>(&kr[c].y));
        float2 f2 = __bfloat1622float2(*reinterpret_cast<__nv_bfloat162*>(&kr[c].z));
        float2 f3 = __bfloat1622float2(*reinterpret_cast<__nv_bfloat162*>(&kr[c].w));
        float4 va = *(const float4*)(vh + c * 256);
        float4 vb = *(const float4*)(vh + c * 256 + 4);
        s += f0.x * va.x + f0.y * va.y + f1.x * va.z + f1.y * va.w;
        s += f2.x * vb.x + f2.y * vb.y + f3.x * vb.z + f3.y * vb.w;
    }
#pragma unroll
    for (int o = 16; o > 0; o >>= 1) s += __shfl_xor_sync(0xffffffffu, s, o);
    if (lane == 0) ps[warp] = s;
    __syncthreads();
    if (tid < 4)
        xout[blockIdx.x * 4 + tid] = (1.0f / N) / (ps[2 * tid] + ps[2 * tid + 1] + 1e-8f);
}

// ---- coupling = u * exp(-C/8) * v ; vectorized around the +1 misalignment ----
__global__ void final_kernel(float* __restrict__ out) {
    int row = blockIdx.x, tid = threadIdx.x;
    float u = g_u[row];
    const float* Crow = out + OUT_C + (size_t)row * N;
    float* Prow = out + OUT_P + (size_t)row * N;
    float ls = 0.f;
    if (tid == 0) {
#pragma unroll
        for (int j = 0; j < 3; j++) {
            float C = Crow[j];
            float cp = u * __expf(-0.125f * C) * g_v[j];
            Prow[j] = cp;
            ls += cp * C;
        }
    } else if (tid == 1) {
        float C = Crow[4095];
        float cp = u * __expf(-0.125f * C) * g_v[4095];
        Prow[4095] = cp;
        ls += cp * C;
    }
#pragma unroll 4
    for (int q = tid; q < 1023; q += 256) {
        int j = 3 + 4 * q;
        float4 C4 = __ldcs((const float4*)(Crow + j));
        float4 p;
        p.x = u * __expf(-0.125f * C4.x) * g_v[j];
        p.y = u * __expf(-0.125f * C4.y) * g_v[j + 1];
        p.z = u * __expf(-0.125f * C4.z) * g_v[j + 2];
        p.w = u * __expf(-0.125f * C4.w) * g_v[j + 3];
        __stcs((float4*)(Prow + j), p);
        ls += p.x * C4.x + p.y * C4.y + p.z * C4.z + p.w * C4.w;
    }
    __shared__ float red[256];
    red[tid] = ls;
    __syncthreads();
    for (int o = 128; o > 0; o >>= 1) {
        if (tid < o) red[tid] += red[tid + o];
        __syncthreads();
    }
    if (tid == 0) g_part[row] = red[0];
}

__global__ void loss_kernel(float* __restrict__ out) {
    int tid = threadIdx.x;
    float s = 0.f;
#pragma unroll
    for (int q = 0; q < 16; q++) s += g_part[tid + q * 256];
    __shared__ float red[256];
    red[tid] = s;
    __syncthreads();
    for (int o = 128; o > 0; o >>= 1) {
        if (tid < o) red[tid] += red[tid + o];
        __syncthreads();
    }
    if (tid == 0) out[0] = red[0] * (1.0f / ((float)N * (float)N));
}

extern "C" void kernel_launch(void* const* d_in, const int* in_sizes, int n_in,
                              void* d_out, int out_size) {
    const float* S  = (const float*)d_in[0];
    const float* Tm = (const float*)d_in[1];
    float* out = (float*)d_out;

    __nv_bfloat16 *dSb, *dTb, *dK, *dKT;
    float *dSn, *dTn, *dU, *dV;
    cudaGetSymbolAddress((void**)&dSb, g_Sb);
    cudaGetSymbolAddress((void**)&dTb, g_Tb);
    cudaGetSymbolAddress((void**)&dK,  g_Kb);
    cudaGetSymbolAddress((void**)&dKT, g_KT);
    cudaGetSymbolAddress((void**)&dSn, g_sn);
    cudaGetSymbolAddress((void**)&dTn, g_tn);
    cudaGetSymbolAddress((void**)&dU,  g_u);
    cudaGetSymbolAddress((void**)&dV,  g_v);

    cudaFuncSetAttribute(gemm_kernel, cudaFuncAttributeMaxDynamicSharedMemorySize, GSMEM);

    cvt_norm_kernel<<<2048, 256>>>(S, dSb, dSn, 0);
    cvt_norm_kernel<<<2048, 256>>>(Tm, dTb, dTn, 1);
    gemm_kernel<<<dim3(32, 32), 256, GSMEM>>>(out);
    for (int it = 0; it < 10; it++) {
        row_kernel<<<1024, 256>>>(dK,  dV, dU);   // u = a/(K v)
        row_kernel<<<1024, 256>>>(dKT, dU, dV);   // v = b/(K^T u)
    }
    final_kernel<<<4096, 256>>>(out);
    loss_kernel<<<1, 256>>>(out);
}

// round 16
// speedup vs baseline: 1.6548x; 1.3097x over previous
#include <cuda_runtime.h>
#include <cuda_bf16.h>
#include <cstdint>

#define N 4096
#define D 512
#define NN ((size_t)N * (size_t)N)
#define OUT_P 1
#define OUT_C (1 + 16777216)

// ---- device scratch (no allocations allowed) ----
__device__ __align__(16) __nv_bfloat16 g_Kb[NN];            // 32 MB bf16 K
__device__ __align__(16) __nv_bfloat16 g_KT[NN];            // 32 MB bf16 K^T
__device__ __align__(16) __nv_bfloat16 g_Sb[(size_t)N * D];
__device__ __align__(16) __nv_bfloat16 g_Tb[(size_t)N * D];
__device__ __align__(16) float g_sn[N], g_tn[N];
__device__ __align__(16) float g_u[N], g_v[N];
__device__ __align__(16) float g_part[N];

// ---- L2 evict_last via cache-hint policy ----
__device__ __forceinline__ uint64_t evict_last_policy() {
    uint64_t pol;
    asm("createpolicy.fractional.L2::evict_last.b64 %0, 1.0;" : "=l"(pol));
    return pol;
}
__device__ __forceinline__ void stG4(void* p, uint32_t v, uint64_t pol) {
    asm volatile("st.global.L2::cache_hint.u32 [%0], %1, %2;"
                 :: "l"(p), "r"(v), "l"(pol));
}
__device__ __forceinline__ void stG16(void* p, uint4 v, uint64_t pol) {
    asm volatile("st.global.L2::cache_hint.v4.u32 [%0], {%1,%2,%3,%4}, %5;"
                 :: "l"(p), "r"(v.x), "r"(v.y), "r"(v.z), "r"(v.w), "l"(pol));
}

// bf16 m16n8k16 mma, fp32 accumulate
__device__ __forceinline__ void mma16(float* c, const uint32_t* a, const uint32_t* b) {
    asm volatile(
        "mma.sync.aligned.m16n8k16.row.col.f32.bf16.bf16.f32 "
        "{%0,%1,%2,%3},{%4,%5,%6,%7},{%8,%9},{%0,%1,%2,%3};"
        : "+f"(c[0]), "+f"(c[1]), "+f"(c[2]), "+f"(c[3])
        : "r"(a[0]), "r"(a[1]), "r"(a[2]), "r"(a[3]), "r"(b[0]), "r"(b[1]));
}

// ---- TMA 1D bulk + mbarrier helpers ----
__device__ __forceinline__ uint32_t smem_u32(const void* p) {
    return (uint32_t)__cvta_generic_to_shared(p);
}
__device__ __forceinline__ void mbar_init(uint32_t a, uint32_t cnt) {
    asm volatile("mbarrier.init.shared.b64 [%0], %1;" :: "r"(a), "r"(cnt) : "memory");
}
__device__ __forceinline__ void mbar_expect_tx(uint32_t a, uint32_t bytes) {
    asm volatile("mbarrier.arrive.expect_tx.shared.b64 _, [%0], %1;"
                 :: "r"(a), "r"(bytes) : "memory");
}
__device__ __forceinline__ void bulk_g2s(uint32_t dst, const void* src,
                                         uint32_t bytes, uint32_t mbar) {
    asm volatile("cp.async.bulk.shared::cluster.global.mbarrier::complete_tx::bytes "
                 "[%0], [%1], %2, [%3];"
                 :: "r"(dst), "l"(src), "r"(bytes), "r"(mbar) : "memory");
}
__device__ __forceinline__ void mbar_wait(uint32_t a, uint32_t parity) {
    uint32_t done = 0;
    while (!done)
        asm volatile("{\n\t.reg .pred p;\n\t"
                     "mbarrier.try_wait.parity.acquire.cta.shared::cta.b64 p, [%1], %2, 0x989680;\n\t"
                     "selp.b32 %0, 1, 0, p;\n\t}"
                     : "=r"(done) : "r"(a), "r"(parity) : "memory");
}

// ---- fused convert fp32->bf16 + row sq-norms (+ optional v0 = 1) ----
__global__ void cvt_norm_kernel(const float* __restrict__ X, __nv_bfloat16* __restrict__ Y,
                                float* __restrict__ nrm, int setv) {
    __shared__ float ws[8];
    int tid = threadIdx.x;
    if (setv && blockIdx.x < 16) g_v[blockIdx.x * 256 + tid] = 1.0f;
    size_t base = (size_t)blockIdx.x * 1024 + tid * 4;
    float4 a = *(const float4*)(X + base);
    uint2 o;
    __nv_bfloat162 lo = __floats2bfloat162_rn(a.x, a.y);
    __nv_bfloat162 hi = __floats2bfloat162_rn(a.z, a.w);
    o.x = *(uint32_t*)&lo;
    o.y = *(uint32_t*)&hi;
    *(uint2*)(Y + base) = o;
    float s = a.x * a.x + a.y * a.y + a.z * a.z + a.w * a.w;
#pragma unroll
    for (int of = 16; of > 0; of >>= 1) s += __shfl_xor_sync(0xffffffffu, s, of);
    if ((tid & 31) == 0) ws[tid >> 5] = s;
    __syncthreads();
    if (tid == 0)   nrm[blockIdx.x * 2]     = ws[0] + ws[1] + ws[2] + ws[3];
    if (tid == 128) nrm[blockIdx.x * 2 + 1] = ws[4] + ws[5] + ws[6] + ws[7];
}

// ---- bf16 tensor-core GEMM (proven R10 mainloop) + C / K / K^T epilogue ----
__global__ void __launch_bounds__(256) gemm_kernel(float* __restrict__ out) {
    __shared__ __align__(16) char smem_all[2 * 128 * 80 * 2];
    char (*As)[128 * 80] = (char(*)[128 * 80])smem_all;
    char (*Bs)[128 * 80] = (char(*)[128 * 80])(smem_all + 2 * 128 * 80);
    const int tid  = threadIdx.x;
    const int lane = tid & 31, warp = tid >> 5;
    const int wm = warp & 1, wn = warp >> 1;
    const int quad = lane >> 2, tb = (lane & 3) * 4;
    const int bi = blockIdx.y, bj = blockIdx.x;

    float acc[4][4][4];
#pragma unroll
    for (int a = 0; a < 4; a++)
#pragma unroll
        for (int b = 0; b < 4; b++)
#pragma unroll
            for (int r = 0; r < 4; r++) acc[a][b][r] = 0.f;

    const __nv_bfloat16* Sb = g_Sb + (size_t)bi * 128 * D;
    const __nv_bfloat16* Tb = g_Tb + (size_t)bj * 128 * D;

    auto load_chunk = [&](int kc, int buf) {
#pragma unroll
        for (int q = 0; q < 2; q++) {
            int f = tid + 256 * q;
            int r = f >> 2, seg = f & 3;
            const __nv_bfloat16* sa = Sb + (size_t)r * D + kc + seg * 8;
            const __nv_bfloat16* sb = Tb + (size_t)r * D + kc + seg * 8;
            uint32_t da = (uint32_t)__cvta_generic_to_shared(&As[buf][r * 80 + seg * 16]);
            uint32_t db = (uint32_t)__cvta_generic_to_shared(&Bs[buf][r * 80 + seg * 16]);
            asm volatile("cp.async.cg.shared.global [%0], [%1], 16;\n\t"
                         "cp.async.cg.shared.global [%2], [%3], 16;"
                         :: "r"(da), "l"(sa), "r"(db), "l"(sb));
        }
        asm volatile("cp.async.commit_group;");
    };

    load_chunk(0, 0);
    for (int c = 0; c < 16; c++) {
        if (c + 1 < 16) {
            load_chunk((c + 1) * 32, (c + 1) & 1);
            asm volatile("cp.async.wait_group 1;");
        } else {
            asm volatile("cp.async.wait_group 0;");
        }
        __syncthreads();
        const char* Ab = As[c & 1];
        const char* Bb = Bs[c & 1];
#pragma unroll
        for (int s = 0; s < 2; s++) {
            const int kb = s * 32 + tb;
            uint32_t aF[4][4], bF[4][2];
#pragma unroll
            for (int mi = 0; mi < 4; mi++) {
                int row = wm * 64 + mi * 16 + quad;
                aF[mi][0] = *(const uint32_t*)(Ab + row * 80 + kb);
                aF[mi][1] = *(const uint32_t*)(Ab + (row + 8) * 80 + kb);
                aF[mi][2] = *(const uint32_t*)(Ab + row * 80 + kb + 16);
                aF[mi][3] = *(const uint32_t*)(Ab + (row + 8) * 80 + kb + 16);
            }
#pragma unroll
            for (int ni = 0; ni < 4; ni++) {
                int nr = wn * 32 + ni * 8 + quad;
                bF[ni][0] = *(const uint32_t*)(Bb + nr * 80 + kb);
                bF[ni][1] = *(const uint32_t*)(Bb + nr * 80 + kb + 16);
            }
#pragma unroll
            for (int mi = 0; mi < 4; mi++)
#pragma unroll
                for (int ni = 0; ni < 4; ni++) mma16(acc[mi][ni], aF[mi], bF[ni]);
        }
        __syncthreads();
    }
    __syncthreads();   // mainloop buffers dead; reuse as ktbuf

    __nv_bfloat16* ktbuf = (__nv_bfloat16*)smem_all;   // [128][136]
    uint64_t pol = evict_last_policy();
    float* outC = out + OUT_C;
#pragma unroll
    for (int mi = 0; mi < 4; mi++) {
#pragma unroll
        for (int ni = 0; ni < 4; ni++) {
            int rl0 = wm * 64 + mi * 16 + quad;
            int cl  = wn * 32 + ni * 8 + (lane & 3) * 2;
            int row0 = bi * 128 + rl0;
            int col  = bj * 128 + cl;
#pragma unroll
            for (int h = 0; h < 2; h++) {
                int rr = row0 + h * 8, rl = rl0 + h * 8;
                float d0 = acc[mi][ni][2 * h], d1 = acc[mi][ni][2 * h + 1];
                float sn = g_sn[rr];
                float c0 = sqrtf(fmaxf(sn + g_tn[col]     - 2.f * d0, 0.f));
                float c1 = sqrtf(fmaxf(sn + g_tn[col + 1] - 2.f * d1, 0.f));
                __stcs(&outC[(size_t)rr * N + col],     c0);
                __stcs(&outC[(size_t)rr * N + col + 1], c1);
                __nv_bfloat162 kk = __floats2bfloat162_rn(__expf(-0.125f * c0),
                                                          __expf(-0.125f * c1));
                stG4(&g_Kb[(size_t)rr * N + col], *(uint32_t*)&kk, pol);
                ktbuf[cl * 136 + rl]       = kk.x;
                ktbuf[(cl + 1) * 136 + rl] = kk.y;
            }
        }
    }
    __syncthreads();
#pragma unroll
    for (int q = 0; q < 8; q++) {
        int idx = tid + 256 * q;
        int j = idx >> 4, seg = idx & 15;
        uint4 v = *(const uint4*)&ktbuf[j * 136 + seg * 8];
        stG16(&g_KT[(size_t)(bj * 128 + j) * N + bi * 128 + seg * 8], v, pol);
    }
}

// ---- TMA-fed scaling pass: o[r] = (1/N) / (sum_j M[r][j] * x[j] + stab) ----
// 512 blocks x 8 rows. K rows arrive via cp.async.bulk into double-buffered
// SMEM (2 rows / 16KB per stage); x held in 16 registers per thread
// (each thread owns the same 16 columns for every row). Per-row partials
// reduced via SMEM + shfl. Bypasses the per-thread LDG issue floor.
__global__ void __launch_bounds__(256) row_tma_kernel(const __nv_bfloat16* __restrict__ M,
                                                      const float* __restrict__ xin,
                                                      float* __restrict__ xout) {
    __shared__ __align__(128) __nv_bfloat16 kbuf[2][2 * N];  // 32 KB
    __shared__ float part[8][256];                            // 8 KB
    __shared__ __align__(8) uint64_t mbar[2];
    const int tid = threadIdx.x;
    const int row0 = blockIdx.x * 8;
    const uint32_t mb[2] = { smem_u32(&mbar[0]), smem_u32(&mbar[1]) };

    if (tid == 0) {
        mbar_init(mb[0], 1);
        mbar_init(mb[1], 1);
        asm volatile("fence.proxy.async.shared::cta;" ::: "memory");
    }
    __syncthreads();

    // x in registers: thread owns cols [c0,c0+8) and [c1,c1+8)
    const int c0 = tid * 8, c1 = 2048 + tid * 8;
    float4 v0 = *(const float4*)(xin + c0);
    float4 v1 = *(const float4*)(xin + c0 + 4);
    float4 v2 = *(const float4*)(xin + c1);
    float4 v3 = *(const float4*)(xin + c1 + 4);

    if (tid == 0) {
        mbar_expect_tx(mb[0], 16384);
        bulk_g2s(smem_u32(&kbuf[0][0]), M + (size_t)row0 * N, 16384, mb[0]);
        mbar_expect_tx(mb[1], 16384);
        bulk_g2s(smem_u32(&kbuf[1][0]), M + (size_t)(row0 + 2) * N, 16384, mb[1]);
    }

    float acc[8];
#pragma unroll
    for (int s = 0; s < 4; s++) {
        mbar_wait(mb[s & 1], (s >> 1) & 1);
#pragma unroll
        for (int r2 = 0; r2 < 2; r2++) {
            const __nv_bfloat16* kp = &kbuf[s & 1][r2 * N];
            uint4 ka = *(const uint4*)(kp + c0);    // conflict-free: banks 4t%32
            uint4 kb2 = *(const uint4*)(kp + c1);
            float2 a0 = __bfloat1622float2(*reinterpret_cast<__nv_bfloat162*>(&ka.x));
            float2 a1 = __bfloat1622float2(*reinterpret_cast<__nv_bfloat162*>(&ka.y));
            float2 a2 = __bfloat1622float2(*reinterpret_cast<__nv_bfloat162*>(&ka.z));
            float2 a3 = __bfloat1622float2(*reinterpret_cast<__nv_bfloat162*>(&ka.w));
            float2 b0 = __bfloat1622float2(*reinterpret_cast<__nv_bfloat162*>(&kb2.x));
            float2 b1 = __bfloat1622float2(*reinterpret_cast<__nv_bfloat162*>(&kb2.y));
            float2 b2 = __bfloat1622float2(*reinterpret_cast<__nv_bfloat162*>(&kb2.z));
            float2 b3 = __bfloat1622float2(*reinterpret_cast<__nv_bfloat162*>(&kb2.w));
            float sdot = a0.x * v0.x + a0.y * v0.y + a1.x * v0.z + a1.y * v0.w
                       + a2.x * v1.x + a2.y * v1.y + a3.x * v1.z + a3.y * v1.w
                       + b0.x * v2.x + b0.y * v2.y + b1.x * v2.z + b1.y * v2.w
                       + b2.x * v3.x + b2.y * v3.y + b3.x * v3.z + b3.y * v3.w;
            acc[2 * s + r2] = sdot;
        }
        __syncthreads();   // buffer fully consumed by all threads
        if (s < 2 && tid == 0) {
            mbar_expect_tx(mb[s & 1], 16384);
            bulk_g2s(smem_u32(&kbuf[s & 1][0]),
                     M + (size_t)(row0 + 2 * (s + 2)) * N, 16384, mb[s & 1]);
        }
    }

#pragma unroll
    for (int r = 0; r < 8; r++) part[r][tid] = acc[r];
    __syncthreads();
    int w = tid >> 5, l = tid & 31;
    float sm = 0.f;
#pragma unroll
    for (int k = 0; k < 8; k++) sm += part[w][l + 32 * k];
#pragma unroll
    for (int o = 16; o > 0; o >>= 1) sm += __shfl_xor_sync(0xffffffffu, sm, o);
    if (l == 0) xout[row0 + w] = (1.0f / N) / (sm + 1e-8f);
}

// ---- coupling = u * exp(-C/8) * v ; vectorized around the +1 misalignment ----
__global__ void final_kernel(float* __restrict__ out) {
    int row = blockIdx.x, tid = threadIdx.x;
    float u = g_u[row];
    const float* Crow = out + OUT_C + (size_t)row * N;
    float* Prow = out + OUT_P + (size_t)row * N;
    float ls = 0.f;
    if (tid == 0) {
#pragma unroll
        for (int j = 0; j < 3; j++) {
            float C = Crow[j];
            float cp = u * __expf(-0.125f * C) * g_v[j];
            Prow[j] = cp;
            ls += cp * C;
        }
    } else if (tid == 1) {
        float C = Crow[4095];
        float cp = u * __expf(-0.125f * C) * g_v[4095];
        Prow[4095] = cp;
        ls += cp * C;
    }
#pragma unroll 4
    for (int q = tid; q < 1023; q += 256) {
        int j = 3 + 4 * q;
        float4 C4 = __ldcs((const float4*)(Crow + j));
        float4 p;
        p.x = u * __expf(-0.125f * C4.x) * g_v[j];
        p.y = u * __expf(-0.125f * C4.y) * g_v[j + 1];
        p.z = u * __expf(-0.125f * C4.z) * g_v[j + 2];
        p.w = u * __expf(-0.125f * C4.w) * g_v[j + 3];
        __stcs((float4*)(Prow + j), p);
        ls += p.x * C4.x + p.y * C4.y + p.z * C4.z + p.w * C4.w;
    }
    __shared__ float red[256];
    red[tid] = ls;
    __syncthreads();
    for (int o = 128; o > 0; o >>= 1) {
        if (tid < o) red[tid] += red[tid + o];
        __syncthreads();
    }
    if (tid == 0) g_part[row] = red[0];
}

__global__ void loss_kernel(float* __restrict__ out) {
    int tid = threadIdx.x;
    float s = 0.f;
#pragma unroll
    for (int q = 0; q < 16; q++) s += g_part[tid + q * 256];
    __shared__ float red[256];
    red[tid] = s;
    __syncthreads();
    for (int o = 128; o > 0; o >>= 1) {
        if (tid < o) red[tid] += red[tid + o];
        __syncthreads();
    }
    if (tid == 0) out[0] = red[0] * (1.0f / ((float)N * (float)N));
}

extern "C" void kernel_launch(void* const* d_in, const int* in_sizes, int n_in,
                              void* d_out, int out_size) {
    const float* S  = (const float*)d_in[0];
    const float* Tm = (const float*)d_in[1];
    float* out = (float*)d_out;

    __nv_bfloat16 *dSb, *dTb, *dK, *dKT;
    float *dSn, *dTn, *dU, *dV;
    cudaGetSymbolAddress((void**)&dSb, g_Sb);
    cudaGetSymbolAddress((void**)&dTb, g_Tb);
    cudaGetSymbolAddress((void**)&dK,  g_Kb);
    cudaGetSymbolAddress((void**)&dKT, g_KT);
    cudaGetSymbolAddress((void**)&dSn, g_sn);
    cudaGetSymbolAddress((void**)&dTn, g_tn);
    cudaGetSymbolAddress((void**)&dU,  g_u);
    cudaGetSymbolAddress((void**)&dV,  g_v);

    cvt_norm_kernel<<<2048, 256>>>(S, dSb, dSn, 0);
    cvt_norm_kernel<<<2048, 256>>>(Tm, dTb, dTn, 1);
    gemm_kernel<<<dim3(32, 32), 256>>>(out);
    for (int it = 0; it < 10; it++) {
        row_tma_kernel<<<512, 256>>>(dK,  dV, dU);   // u = a/(K v)
        row_tma_kernel<<<512, 256>>>(dKT, dU, dV);   // v = b/(K^T u)
    }
    final_kernel<<<4096, 256>>>(out);
    loss_kernel<<<1, 256>>>(out);
}